// round 15
// baseline (speedup 1.0000x reference)
#include <cuda_runtime.h>
#include <cuda_bf16.h>

// HGNN forward, ONE kernel. 128 blocks x 512 threads; each block processes
// TWO graphs concurrently (half-block each), sharing one W tile.
//   M[e,d]  = (1/32) * sum_v H[v,e]*x[v,d]
//   ED[e,f] = relu(sum_d M[e,d]*W[f,d] + b[f])  -> h_e
//   c[f]    = (1/(32*48)) sum_e s[e]*ED[e,f]
// Output buffer: [ c (B*D) | h_e (B*E*D) ]
//
// R15 = R14 design fitted under the 48KB static-shared cap: Ht and Ms share
// one pool (Ht dead after phase 1; phase-1 results ride in registers across
// a sync, then land on top of Ht). 24K pool + 17K Ws + 4.7K misc = 46.7KB.

constexpr int V   = 8192;
constexpr int E   = 48;
constexpr int D   = 64;
constexpr int B   = 256;
constexpr int NPG = V / B;     // 32 nodes per graph
constexpr int NT  = 512;       // 2 x 256
constexpr int HT_ = 256;       // threads per graph half
constexpr int WS  = 68;        // W shared row stride (floats)

typedef unsigned long long ull;

__device__ __forceinline__ void ffma2(ull& acc, ull a, ull b) {
    asm("fma.rn.f32x2 %0, %1, %2, %0;" : "+l"(acc) : "l"(a), "l"(b));
}
__device__ __forceinline__ ull pack2(float lo, float hi) {
    ull r;
    asm("mov.b64 %0, {%1, %2};" : "=l"(r) : "f"(lo), "f"(hi));
    return r;
}
__device__ __forceinline__ float sum2(ull v) {
    float lo, hi;
    asm("mov.b64 {%0, %1}, %2;" : "=f"(lo), "=f"(hi) : "l"(v));
    return lo + hi;
}

__global__ __launch_bounds__(NT, 1) void hgnn_kernel(
    const float* __restrict__ x,     // (V, D)
    const float* __restrict__ Hm,    // (V, E)
    const float* __restrict__ W,     // (D, D) row-major [f][d]
    const float* __restrict__ bias,  // (D,)
    float* __restrict__ out)         // [c | h_e]
{
    // Pool: phase 1 uses it as Ht[2][E*NPG] (12KB of it);
    // after the post-phase1 sync it becomes Ms[2][E*D] (all 24KB).
    __shared__ float Pool[2 * E * D];   // 24 KB
    __shared__ float Ws[D * WS];        // 17 KB (shared by both graphs)
    __shared__ float Sv[2][E];
    __shared__ float Bs[D];
    __shared__ float Cp[2][8][D];       // 4 KB

    const int t    = threadIdx.x;
    const int half = t >> 8;            // 0/1 -> which graph
    const int tt   = t & 255;           // tid within half
    const int b    = blockIdx.x * 2 + half;   // graph id

    float* Hth = Pool + half * (E * NPG);   // this half's Ht
    float* Msh = Pool + half * (E * D);     // this half's Ms (after alias flip)

    // ---- stage W rows + bias (whole block, once per TWO graphs) ----
    #pragma unroll
    for (int i = t; i < D * D / 4; i += NT) {          // 1024 float4
        float4 w = ((const float4*)W)[i];
        int fw = i >> 4, d4 = (i & 15) * 4;
        *(float4*)&Ws[fw * WS + d4] = w;
    }
    if (t < D) Bs[t] = bias[t];

    // ---- stage this half's H transposed (coalesced) ----
    {
        const float4* hb = (const float4*)(Hm + (size_t)b * NPG * E);
        #pragma unroll
        for (int i = tt; i < NPG * E / 4; i += HT_) {   // 384; E%4==0
            float4 h = hb[i];
            int base = i * 4;
            int v = base / E;
            int e = base - v * E;
            Hth[(e + 0) * NPG + v] = h.x;
            Hth[(e + 1) * NPG + v] = h.y;
            Hth[(e + 2) * NPG + v] = h.z;
            Hth[(e + 3) * NPG + v] = h.w;
        }
    }
    __syncthreads();

    // ---- s[e] = sum_v Ht[e,v] (reads Ht before it is overwritten) ----
    if (tt < E) {
        const float4* hr = (const float4*)&Hth[tt * NPG];
        float a0 = 0.f, a1 = 0.f;
        #pragma unroll
        for (int k = 0; k < NPG / 8; k++) {
            float4 h0 = hr[2 * k], h1 = hr[2 * k + 1];
            a0 += h0.x + h0.y + h0.z + h0.w;
            a1 += h1.x + h1.y + h1.z + h1.w;
        }
        Sv[half][tt] = a0 + a1;
    }

    // ---- phase 1: M[e,f] accumulated in REGISTERS; f = tt&63, qq = tt>>6 ----
    const int f = tt & 63, qq = tt >> 6;
    ull macc2[12];
    #pragma unroll
    for (int j = 0; j < 12; j++) macc2[j] = 0;

    #pragma unroll
    for (int vc = 0; vc < 2; vc++) {
        float xr[16];
        const float* xg = x + (size_t)b * NPG * D + (vc * 16) * D + f;
        #pragma unroll
        for (int v = 0; v < 16; v++) xr[v] = xg[v * D];   // coalesced LDG

        ull xp[8];
        #pragma unroll
        for (int k = 0; k < 8; k++) xp[k] = pack2(xr[2 * k], xr[2 * k + 1]);

        #pragma unroll
        for (int j = 0; j < 12; j++) {
            int e = j * 4 + qq;
            const ulonglong2* hr = (const ulonglong2*)&Hth[e * NPG + vc * 16];
            #pragma unroll
            for (int k = 0; k < 4; k++) {
                ulonglong2 h = hr[k];
                ffma2(macc2[j], h.x, xp[2 * k + 0]);
                ffma2(macc2[j], h.y, xp[2 * k + 1]);
            }
        }
    }
    __syncthreads();   // everyone done READING Ht (and Sv written)

    // ---- alias flip: write Ms over the Ht region ----
    #pragma unroll
    for (int j = 0; j < 12; j++)
        Msh[(j * 4 + qq) * D + f] = sum2(macc2[j]) * (1.0f / NPG);
    __syncthreads();

    // ---- phase 2: tile (6e x 2f); u = tt&31, es = tt>>5; e = j*8+es ----
    {
        const int u = tt & 31, es = tt >> 5;
        ull acc2a[6], acc2b[6];
        #pragma unroll
        for (int j = 0; j < 6; j++) { acc2a[j] = 0; acc2b[j] = 0; }

        #pragma unroll
        for (int dc = 0; dc < 4; dc++) {
            ulonglong2 wa[4], wb[4];
            const ulonglong2* wra = (const ulonglong2*)&Ws[u * WS + dc * 16];
            const ulonglong2* wrb = (const ulonglong2*)&Ws[(u + 32) * WS + dc * 16];
            #pragma unroll
            for (int k = 0; k < 4; k++) { wa[k] = wra[k]; wb[k] = wrb[k]; }

            #pragma unroll
            for (int j = 0; j < 6; j++) {
                int e = j * 8 + es;
                const ulonglong2* mr = (const ulonglong2*)&Msh[e * D + dc * 16]; // bcast
                #pragma unroll
                for (int k = 0; k < 4; k++) {
                    ulonglong2 m = mr[k];
                    ffma2(acc2a[j], m.x, wa[k].x);
                    ffma2(acc2a[j], m.y, wa[k].y);
                    ffma2(acc2b[j], m.x, wb[k].x);
                    ffma2(acc2b[j], m.y, wb[k].y);
                }
            }
        }

        // relu, h_e store, c fold
        float c0 = 0.f, c1 = 0.f;
        float* he = out + (size_t)B * D + (size_t)b * E * D;
        const float bf0 = Bs[u], bf1 = Bs[u + 32];
        #pragma unroll
        for (int j = 0; j < 6; j++) {
            int e = j * 8 + es;
            float r0 = fmaxf(sum2(acc2a[j]) + bf0, 0.f);
            float r1 = fmaxf(sum2(acc2b[j]) + bf1, 0.f);
            he[e * D + u]      = r0;     // coalesced
            he[e * D + u + 32] = r1;     // coalesced
            float sv = Sv[half][e];
            c0 = fmaf(sv, r0, c0);
            c1 = fmaf(sv, r1, c1);
        }
        Cp[half][es][u]      = c0;
        Cp[half][es][u + 32] = c1;
    }
    __syncthreads();

    // ---- c: all 48 e local to this half -> direct write ----
    if (tt < D) {
        float s = 0.f;
        #pragma unroll
        for (int k = 0; k < 8; k++) s += Cp[half][k][tt];
        out[b * D + tt] = s * (1.0f / (NPG * E));
    }
}

extern "C" void kernel_launch(void* const* d_in, const int* in_sizes, int n_in,
                              void* d_out, int out_size) {
    const float* x    = (const float*)d_in[0];   // (V,D)
    const float* Hm   = (const float*)d_in[1];   // (V,E)
    const float* W    = (const float*)d_in[2];   // (D,D)
    const float* bias = (const float*)d_in[3];   // (D,)
    float* out = (float*)d_out;

    hgnn_kernel<<<B / 2, NT>>>(x, Hm, W, bias, out);
}